// round 2
// baseline (speedup 1.0000x reference)
#include <cuda_runtime.h>
#include <cstdint>

#define NB 16
#define NL 1024
#define ND 512
#define NH 256
#define NK 4
#define NROWS (NB * NL)   // 16384

// ---------------- scratch (static device globals; no allocs) ----------------
__device__ float    g_sel [NROWS * NK];     // softmax selections     (1 MB)
__device__ float    g_uin [NROWS * NH];     // x @ W_B^T              (16 MB)
__device__ float    g_invn[NROWS * NH];     // 1/norm per (row, j)    (16 MB)
__device__ float    g_buf [2][NB][NH];      // h_new accumulators (parity)
__device__ unsigned g_bar [NB];             // per-batch barrier counters

// ---------------- init: reset barrier + accumulators every launch -----------
__global__ void init_kernel() {
    int tid = blockIdx.x * blockDim.x + threadIdx.x;
    if (tid < 2 * NB * NH) ((float*)g_buf)[tid] = 0.0f;
    if (tid < NB) g_bar[tid] = 0u;
}

// ---------------- kernel 1: selection logits + softmax ----------------------
// one warp per row; W_sel (4x512) cached in smem
__global__ __launch_bounds__(256) void sel_kernel(
    const float* __restrict__ x, const float* __restrict__ Wsel,
    const float* __restrict__ bsel)
{
    __shared__ float Ws[NK * ND];
    for (int i = threadIdx.x; i < NK * ND; i += blockDim.x) Ws[i] = Wsel[i];
    __syncthreads();

    int w = threadIdx.x >> 5, l = threadIdx.x & 31;
    int row = blockIdx.x * 8 + w;
    const float* xr = x + row * ND;

    float p0 = 0.f, p1 = 0.f, p2 = 0.f, p3 = 0.f;
    for (int d = l; d < ND; d += 32) {
        float xv = xr[d];
        p0 += xv * Ws[d];
        p1 += xv * Ws[ND + d];
        p2 += xv * Ws[2 * ND + d];
        p3 += xv * Ws[3 * ND + d];
    }
#pragma unroll
    for (int o = 16; o > 0; o >>= 1) {
        p0 += __shfl_xor_sync(0xffffffffu, p0, o);
        p1 += __shfl_xor_sync(0xffffffffu, p1, o);
        p2 += __shfl_xor_sync(0xffffffffu, p2, o);
        p3 += __shfl_xor_sync(0xffffffffu, p3, o);
    }
    if (l == 0) {
        float l0 = p0 + bsel[0], l1 = p1 + bsel[1], l2 = p2 + bsel[2], l3 = p3 + bsel[3];
        float m = fmaxf(fmaxf(l0, l1), fmaxf(l2, l3));
        float e0 = __expf(l0 - m), e1 = __expf(l1 - m), e2 = __expf(l2 - m), e3 = __expf(l3 - m);
        float inv = 1.0f / (e0 + e1 + e2 + e3);
        float4 out = make_float4(e0 * inv, e1 * inv, e2 * inv, e3 * inv);
        *reinterpret_cast<float4*>(&g_sel[row * NK]) = out;
    }
}

// ---------------- kernel 2: u = x @ W_B^T  (M=16384, N=256, K=512) ----------
// 64x64 tile, BK=16, 4x4 register blocking, 256 threads
__global__ __launch_bounds__(256) void uin_kernel(
    const float* __restrict__ X, const float* __restrict__ Wb)
{
    __shared__ float Xs[16][64];
    __shared__ float Wt[16][64];
    int m0 = blockIdx.y * 64;
    int n0 = blockIdx.x * 64;
    int tid = threadIdx.x;
    int tx = tid & 15, ty = tid >> 4;
    int lr = tid >> 2, lq = tid & 3;

    float acc[4][4];
#pragma unroll
    for (int r = 0; r < 4; r++)
#pragma unroll
        for (int c = 0; c < 4; c++) acc[r][c] = 0.f;

    for (int k0 = 0; k0 < ND; k0 += 16) {
        float4 xv = *reinterpret_cast<const float4*>(&X [(m0 + lr) * ND + k0 + lq * 4]);
        float4 wv = *reinterpret_cast<const float4*>(&Wb[(n0 + lr) * ND + k0 + lq * 4]);
        __syncthreads();
        Xs[lq * 4 + 0][lr] = xv.x; Xs[lq * 4 + 1][lr] = xv.y;
        Xs[lq * 4 + 2][lr] = xv.z; Xs[lq * 4 + 3][lr] = xv.w;
        Wt[lq * 4 + 0][lr] = wv.x; Wt[lq * 4 + 1][lr] = wv.y;
        Wt[lq * 4 + 2][lr] = wv.z; Wt[lq * 4 + 3][lr] = wv.w;
        __syncthreads();
#pragma unroll
        for (int kk = 0; kk < 16; kk++) {
            float4 a = *reinterpret_cast<const float4*>(&Xs[kk][ty * 4]);
            float4 b = *reinterpret_cast<const float4*>(&Wt[kk][tx * 4]);
            acc[0][0] += a.x * b.x; acc[0][1] += a.x * b.y; acc[0][2] += a.x * b.z; acc[0][3] += a.x * b.w;
            acc[1][0] += a.y * b.x; acc[1][1] += a.y * b.y; acc[1][2] += a.y * b.z; acc[1][3] += a.y * b.w;
            acc[2][0] += a.z * b.x; acc[2][1] += a.z * b.y; acc[2][2] += a.z * b.z; acc[2][3] += a.z * b.w;
            acc[3][0] += a.w * b.x; acc[3][1] += a.w * b.y; acc[3][2] += a.w * b.z; acc[3][3] += a.w * b.w;
        }
    }
#pragma unroll
    for (int r = 0; r < 4; r++) {
        float4 o = make_float4(acc[r][0], acc[r][1], acc[r][2], acc[r][3]);
        *reinterpret_cast<float4*>(&g_uin[(m0 + ty * 4 + r) * NH + n0 + tx * 4]) = o;
    }
}

// ---------------- kernel 3: inv_norm pre-pass -------------------------------
// Per (row, j): invn = (sum_i |sum_k s_k A[i][j][k]|^1.2)^(-1/1.2)
// Fully parallel — the pow-heavy work hoisted out of the sequential scan.
#define JC 8
__global__ __launch_bounds__(256) void norm_kernel(const float* __restrict__ A)
{
    __shared__ float4 As[JC * NH];   // 32 KB: A[ :, jbase..jbase+7, 0..3]
    int jbase = blockIdx.x * JC;
    for (int idx = threadIdx.x; idx < JC * NH; idx += blockDim.x) {
        int jl = idx >> 8, i = idx & 255;
        As[idx] = reinterpret_cast<const float4*>(A)[i * NH + jbase + jl];
    }
    __syncthreads();

    int w = threadIdx.x >> 5, l = threadIdx.x & 31;
    int row0 = blockIdx.y * (NROWS / 32);
    int rowend = row0 + (NROWS / 32);

    for (int row = row0 + w; row < rowend; row += 8) {
        float4 s = *reinterpret_cast<const float4*>(&g_sel[row * NK]);
        float acc[JC];
#pragma unroll
        for (int jl = 0; jl < JC; jl++) acc[jl] = 0.f;
#pragma unroll
        for (int jl = 0; jl < JC; jl++) {
#pragma unroll
            for (int r = 0; r < 8; r++) {
                float4 a4 = As[jl * NH + r * 32 + l];
                float a = fabsf(s.x * a4.x + s.y * a4.y + s.z * a4.z + s.w * a4.w);
                acc[jl] += __powf(a, 1.2f);   // 0^1.2 -> 0 via -inf chain
            }
        }
        float myv = 0.f;
#pragma unroll
        for (int jl = 0; jl < JC; jl++) {
            float v = acc[jl];
            v += __shfl_xor_sync(0xffffffffu, v, 16);
            v += __shfl_xor_sync(0xffffffffu, v, 8);
            v += __shfl_xor_sync(0xffffffffu, v, 4);
            v += __shfl_xor_sync(0xffffffffu, v, 2);
            v += __shfl_xor_sync(0xffffffffu, v, 1);
            if (l == jl) myv = v;
        }
        if (l < JC) g_invn[row * NH + jbase + l] = __powf(myv, -1.0f / 1.2f);
    }
}

// ---------------- kernel 4: the scan (persistent, 128 CTAs) -----------------
// CTA (b, slice): owns 32 columns j AND the matching 32 rows i of h.
// A slice held entirely in registers (16 x float4 per thread).
// h_new_i = sum_j (sum_k s_k A_ijk) * (h_j * invn_j); cross-CTA reduction via
// L2 float atomics into parity-double-buffered accumulators; one per-batch
// global barrier per step.
__global__ __launch_bounds__(512, 1) void scan_kernel(
    const float* __restrict__ A, float* __restrict__ out)
{
    int b = blockIdx.x >> 3;
    int slice = blockIdx.x & 7;
    int jbase = slice * 32;
    int tid = threadIdx.x;
    int w = tid >> 5, l = tid & 31;
    int jj = l >> 4, ii = l & 15;
    int jloc = (w << 1) | jj;        // 0..31
    int j = jbase + jloc;

    float4 Areg[16];                 // A[i = 16r+ii][j][0..3]
#pragma unroll
    for (int r = 0; r < 16; r++) {
        int i = r * 16 + ii;
        Areg[r] = reinterpret_cast<const float4*>(A)[i * NH + j];
    }

    __shared__ float h_sm[32];
    __shared__ float y_sm[32];
    __shared__ float s_sm[4];
    __shared__ float red_sm[16][256];

    if (tid < 32) h_sm[tid] = 0.f;
    __syncthreads();

    const int rowbase = b * NL;
    for (int t = 0; t < NL; t++) {
        const int row = rowbase + t;
        if (tid < 32) y_sm[tid] = h_sm[tid] * __ldg(&g_invn[row * NH + jbase + tid]);
        if (tid < 4)  s_sm[tid] = __ldg(&g_sel[row * NK + tid]);
        __syncthreads();

        float s0 = s_sm[0], s1 = s_sm[1], s2 = s_sm[2], s3 = s_sm[3];
        float y = y_sm[jloc];
        float part[16];
#pragma unroll
        for (int r = 0; r < 16; r++) {
            float a = s0 * Areg[r].x + s1 * Areg[r].y + s2 * Areg[r].z + s3 * Areg[r].w;
            part[r] = a * y;
        }
#pragma unroll
        for (int r = 0; r < 16; r++)
            part[r] += __shfl_xor_sync(0xffffffffu, part[r], 16);
        if (jj == 0) {
#pragma unroll
            for (int r = 0; r < 16; r++)
                red_sm[w][r * 16 + ii] = part[r];
        }
        __syncthreads();

        if (tid < 256) {
            float sum = 0.f;
#pragma unroll
            for (int w2 = 0; w2 < 16; w2++) sum += red_sm[w2][tid];
            atomicAdd(&g_buf[t & 1][b][tid], sum);
        }
        __threadfence();
        __syncthreads();

        if (tid == 0) {
            atomicAdd(&g_bar[b], 1u);
            unsigned target = (unsigned)(t + 1) * 8u;
            while (*(volatile unsigned*)&g_bar[b] < target) { }
            __threadfence();
        }
        __syncthreads();

        if (tid < 32) {
            float hv = __ldcg(&g_buf[t & 1][b][jbase + tid]);
            hv += __ldg(&g_uin[row * NH + jbase + tid]);
            out[row * NH + jbase + tid] = hv;
            h_sm[tid] = hv;
            __stcg(&g_buf[t & 1][b][jbase + tid], 0.0f);  // reset for t+2
        }
        __syncthreads();
    }
}

// ---------------- launch ----------------------------------------------------
extern "C" void kernel_launch(void* const* d_in, const int* in_sizes, int n_in,
                              void* d_out, int out_size)
{
    const float* x     = (const float*)d_in[0];   // (16,1024,512)
    const float* Wsel  = (const float*)d_in[1];   // (4,512)
    const float* bsel  = (const float*)d_in[2];   // (4,)
    const float* Wb    = (const float*)d_in[3];   // (256,512)
    const float* Adict = (const float*)d_in[4];   // (256,256,4)
    float* out = (float*)d_out;                   // (16,1024,256)

    init_kernel<<<32, 256>>>();
    sel_kernel<<<NROWS / 8, 256>>>(x, Wsel, bsel);
    uin_kernel<<<dim3(NH / 64, NROWS / 64), 256>>>(x, Wb);
    norm_kernel<<<dim3(NH / JC, 32), 256>>>(Adict);
    scan_kernel<<<NB * 8, 512>>>(Adict, out);
}

// round 4
// speedup vs baseline: 1.4861x; 1.4861x over previous
#include <cuda_runtime.h>
#include <cstdint>

#define NB 16
#define NL 1024
#define ND 512
#define NH 256
#define NK 4
#define NROWS (NB * NL)   // 16384

// ---------------- scratch (static device globals; no allocs) ----------------
__device__ float g_sel [NROWS * NK];     // softmax selections     (256 KB)
__device__ float g_uin [NROWS * NH];     // x @ W_B^T              (16 MB)
__device__ float g_invn[NROWS * NH];     // 1/norm per (row, j)    (16 MB)

// ---------------- helpers ----------------------------------------------------
__device__ __forceinline__ float fast_lg2(float x) {
    float r;
    asm("lg2.approx.f32 %0, %1;" : "=f"(r) : "f"(x));
    return r;
}
__device__ __forceinline__ float fast_ex2(float x) {
    float r;
    asm("ex2.approx.f32 %0, %1;" : "=f"(r) : "f"(x));
    return r;
}
__device__ __forceinline__ uint32_t smem_u32(const void* p) {
    uint32_t a;
    asm("{ .reg .u64 t; cvta.to.shared.u64 t, %1; cvt.u32.u64 %0, t; }"
        : "=r"(a) : "l"(p));
    return a;
}
__device__ __forceinline__ uint32_t mapa_u32(uint32_t a, uint32_t r) {
    uint32_t d;
    asm("mapa.shared::cluster.u32 %0, %1, %2;" : "=r"(d) : "r"(a), "r"(r));
    return d;
}

// ---------------- kernel 1: selection logits + softmax ----------------------
__global__ __launch_bounds__(256) void sel_kernel(
    const float* __restrict__ x, const float* __restrict__ Wsel,
    const float* __restrict__ bsel)
{
    __shared__ float Ws[NK * ND];
    for (int i = threadIdx.x; i < NK * ND; i += blockDim.x) Ws[i] = Wsel[i];
    __syncthreads();

    int w = threadIdx.x >> 5, l = threadIdx.x & 31;
    int row = blockIdx.x * 8 + w;
    const float* xr = x + row * ND;

    float p0 = 0.f, p1 = 0.f, p2 = 0.f, p3 = 0.f;
    for (int d = l; d < ND; d += 32) {
        float xv = xr[d];
        p0 += xv * Ws[d];
        p1 += xv * Ws[ND + d];
        p2 += xv * Ws[2 * ND + d];
        p3 += xv * Ws[3 * ND + d];
    }
#pragma unroll
    for (int o = 16; o > 0; o >>= 1) {
        p0 += __shfl_xor_sync(0xffffffffu, p0, o);
        p1 += __shfl_xor_sync(0xffffffffu, p1, o);
        p2 += __shfl_xor_sync(0xffffffffu, p2, o);
        p3 += __shfl_xor_sync(0xffffffffu, p3, o);
    }
    if (l == 0) {
        float l0 = p0 + bsel[0], l1 = p1 + bsel[1], l2 = p2 + bsel[2], l3 = p3 + bsel[3];
        float m = fmaxf(fmaxf(l0, l1), fmaxf(l2, l3));
        float e0 = __expf(l0 - m), e1 = __expf(l1 - m), e2 = __expf(l2 - m), e3 = __expf(l3 - m);
        float inv = 1.0f / (e0 + e1 + e2 + e3);
        float4 out = make_float4(e0 * inv, e1 * inv, e2 * inv, e3 * inv);
        *reinterpret_cast<float4*>(&g_sel[row * NK]) = out;
    }
}

// ---------------- kernel 2: u = x @ W_B^T  (M=16384, N=256, K=512) ----------
__global__ __launch_bounds__(256) void uin_kernel(
    const float* __restrict__ X, const float* __restrict__ Wb)
{
    __shared__ float Xs[16][64];
    __shared__ float Wt[16][64];
    int m0 = blockIdx.y * 64;
    int n0 = blockIdx.x * 64;
    int tid = threadIdx.x;
    int tx = tid & 15, ty = tid >> 4;
    int lr = tid >> 2, lq = tid & 3;

    float acc[4][4];
#pragma unroll
    for (int r = 0; r < 4; r++)
#pragma unroll
        for (int c = 0; c < 4; c++) acc[r][c] = 0.f;

    for (int k0 = 0; k0 < ND; k0 += 16) {
        float4 xv = *reinterpret_cast<const float4*>(&X [(m0 + lr) * ND + k0 + lq * 4]);
        float4 wv = *reinterpret_cast<const float4*>(&Wb[(n0 + lr) * ND + k0 + lq * 4]);
        __syncthreads();
        Xs[lq * 4 + 0][lr] = xv.x; Xs[lq * 4 + 1][lr] = xv.y;
        Xs[lq * 4 + 2][lr] = xv.z; Xs[lq * 4 + 3][lr] = xv.w;
        Wt[lq * 4 + 0][lr] = wv.x; Wt[lq * 4 + 1][lr] = wv.y;
        Wt[lq * 4 + 2][lr] = wv.z; Wt[lq * 4 + 3][lr] = wv.w;
        __syncthreads();
#pragma unroll
        for (int kk = 0; kk < 16; kk++) {
            float4 a = *reinterpret_cast<const float4*>(&Xs[kk][ty * 4]);
            float4 b = *reinterpret_cast<const float4*>(&Wt[kk][tx * 4]);
            acc[0][0] += a.x * b.x; acc[0][1] += a.x * b.y; acc[0][2] += a.x * b.z; acc[0][3] += a.x * b.w;
            acc[1][0] += a.y * b.x; acc[1][1] += a.y * b.y; acc[1][2] += a.y * b.z; acc[1][3] += a.y * b.w;
            acc[2][0] += a.z * b.x; acc[2][1] += a.z * b.y; acc[2][2] += a.z * b.z; acc[2][3] += a.z * b.w;
            acc[3][0] += a.w * b.x; acc[3][1] += a.w * b.y; acc[3][2] += a.w * b.z; acc[3][3] += a.w * b.w;
        }
    }
#pragma unroll
    for (int r = 0; r < 4; r++) {
        float4 o = make_float4(acc[r][0], acc[r][1], acc[r][2], acc[r][3]);
        *reinterpret_cast<float4*>(&g_uin[(m0 + ty * 4 + r) * NH + n0 + tx * 4]) = o;
    }
}

// ---------------- kernel 3: inv_norm pre-pass (register-resident A) ---------
// grid (32 jblocks, 16 rowgroups), 256 threads. Warp w owns column jl=w of the
// jblock; lane l holds A[l+32r][j][0..3] for r=0..7 in registers. Per row:
// 16 warp-MUFU + 5-shfl reduce. No smem, no spills -> MUFU-pipe bound.
__global__ __launch_bounds__(256, 2) void norm_kernel(const float* __restrict__ A)
{
    int jbase = blockIdx.x * 8;
    int w = threadIdx.x >> 5, l = threadIdx.x & 31;
    int j = jbase + w;

    float4 Ar[8];
#pragma unroll
    for (int r = 0; r < 8; r++)
        Ar[r] = reinterpret_cast<const float4*>(A)[(l + 32 * r) * NH + j];

    const int rows_per_blk = NROWS / 16;       // 1024
    const int row0 = blockIdx.y * rows_per_blk;
    const float ninv = -1.0f / 1.2f;

    for (int row = row0; row < row0 + rows_per_blk; row++) {
        float4 s = __ldg(reinterpret_cast<const float4*>(&g_sel[row * NK]));
        float acc = 0.f;
#pragma unroll
        for (int r = 0; r < 8; r++) {
            float a = fmaf(s.x, Ar[r].x,
                      fmaf(s.y, Ar[r].y,
                      fmaf(s.z, Ar[r].z, s.w * Ar[r].w)));
            float t = a * a;                       // |a|^1.2 = (a^2)^0.6
            acc += fast_ex2(0.6f * fast_lg2(t));
        }
        acc += __shfl_xor_sync(0xffffffffu, acc, 16);
        acc += __shfl_xor_sync(0xffffffffu, acc, 8);
        acc += __shfl_xor_sync(0xffffffffu, acc, 4);
        acc += __shfl_xor_sync(0xffffffffu, acc, 2);
        acc += __shfl_xor_sync(0xffffffffu, acc, 1);
        if (l == 0)
            g_invn[row * NH + j] = fast_ex2(fast_lg2(acc) * ninv);
    }
}

// ---------------- kernel 4: scan with 8-CTA clusters ------------------------
// Cluster = one batch. CTA rank owns 32 j-columns (jbase=rank*32) and the
// matching 32 h rows. Thread t: row i=t>>1, 16 j's (half=t&1). A slice in
// registers. Per step: mix+matvec (reg-only), shfl_xor(1) pairs the halves,
// even threads push the row partial to owner CTA's DSMEM slot (parity
// double-buffered), one cluster barrier, warp0 sums 8 slots + u, stores out.
__global__ __launch_bounds__(512, 1) __cluster_dims__(8, 1, 1)
void scan_kernel(const float* __restrict__ A, float* __restrict__ out)
{
    __shared__ float y_sm[32];
    __shared__ float pbuf[2][8][32];

    int tid = threadIdx.x;
    uint32_t rank;
    asm("mov.u32 %0, %%cluster_ctarank;" : "=r"(rank));
    int b = blockIdx.x >> 3;
    int jbase = (int)rank * 32;
    int i = tid >> 1, half = tid & 1;

    float4 Areg[16];
#pragma unroll
    for (int q = 0; q < 16; q++)
        Areg[q] = reinterpret_cast<const float4*>(A)[i * NH + jbase + half * 16 + q];

    // remote DSMEM destination for this thread's row partial
    uint32_t dst = (uint32_t)(i >> 5);
    uint32_t laddr0 = smem_u32(pbuf) + (rank * 32u + (uint32_t)(i & 31)) * 4u;
    uint32_t raddr0 = mapa_u32(laddr0, dst);
    uint32_t raddr1 = raddr0 + 8u * 32u * 4u;   // parity-1 buffer

    const int rowbase = b * NL;
    float4 s_cur = __ldg(reinterpret_cast<const float4*>(&g_sel[rowbase * NK]));
    float inv_cur = 0.f, u_cur = 0.f, h_reg = 0.f;
    if (tid < 32) {
        inv_cur = __ldg(&g_invn[rowbase * NH + jbase + tid]);
        u_cur   = __ldg(&g_uin [rowbase * NH + jbase + tid]);
    }

    for (int t = 0; t < NL; t++) {
        const int row = rowbase + t;
        if (tid < 32) y_sm[tid] = h_reg * inv_cur;
        __syncthreads();

        // prefetch next-step row data (lands in regs; survives L1 flush)
        const int rown = row + (t < NL - 1 ? 1 : 0);
        float4 s_nxt = __ldg(reinterpret_cast<const float4*>(&g_sel[rown * NK]));
        float inv_nxt = 0.f, u_nxt = 0.f;
        if (tid < 32) {
            inv_nxt = __ldg(&g_invn[rown * NH + jbase + tid]);
            u_nxt   = __ldg(&g_uin [rown * NH + jbase + tid]);
        }

        float acc = 0.f;
#pragma unroll
        for (int q = 0; q < 16; q++) {
            float a = fmaf(s_cur.x, Areg[q].x,
                      fmaf(s_cur.y, Areg[q].y,
                      fmaf(s_cur.z, Areg[q].z, s_cur.w * Areg[q].w)));
            acc = fmaf(a, y_sm[half * 16 + q], acc);
        }
        acc += __shfl_xor_sync(0xffffffffu, acc, 1);

        if (half == 0) {
            uint32_t ra = (t & 1) ? raddr1 : raddr0;
            asm volatile("st.shared::cluster.f32 [%0], %1;" :: "r"(ra), "f"(acc) : "memory");
        }

        // cluster barrier: release orders the DSMEM stores, acquire makes them visible
        asm volatile("barrier.cluster.arrive.aligned;" ::: "memory");
        asm volatile("barrier.cluster.wait.aligned;"  ::: "memory");

        if (tid < 32) {
            float hv = u_cur;
            const float* pb = &pbuf[t & 1][0][tid];
#pragma unroll
            for (int ss = 0; ss < 8; ss++) hv += pb[ss * 32];
            out[row * NH + jbase + tid] = hv;
            h_reg = hv;
            inv_cur = inv_nxt;
            u_cur = u_nxt;
        }
        s_cur = s_nxt;
    }
}

// ---------------- launch ----------------------------------------------------
extern "C" void kernel_launch(void* const* d_in, const int* in_sizes, int n_in,
                              void* d_out, int out_size)
{
    const float* x     = (const float*)d_in[0];   // (16,1024,512)
    const float* Wsel  = (const float*)d_in[1];   // (4,512)
    const float* bsel  = (const float*)d_in[2];   // (4,)
    const float* Wb    = (const float*)d_in[3];   // (256,512)
    const float* Adict = (const float*)d_in[4];   // (256,256,4)
    float* out = (float*)d_out;                   // (16,1024,256)

    sel_kernel<<<NROWS / 8, 256>>>(x, Wsel, bsel);
    uin_kernel<<<dim3(NH / 64, NROWS / 64), 256>>>(x, Wb);
    norm_kernel<<<dim3(32, 16), 256>>>(Adict);
    scan_kernel<<<NB * 8, 512>>>(Adict, out);
}

// round 5
// speedup vs baseline: 2.3202x; 1.5613x over previous
#include <cuda_runtime.h>
#include <cstdint>

#define NB 16
#define NL 1024
#define ND 512
#define NH 256
#define NK 4
#define NROWS (NB * NL)   // 16384

// ---------------- scratch (static device globals; no allocs) ----------------
__device__ float g_sel [NROWS * NK];     // softmax selections     (256 KB)
__device__ float g_uin [NROWS * NH];     // x @ W_B^T              (16 MB)
__device__ float g_invn[NROWS * NH];     // 1/norm per (row, j)    (16 MB)

// ---------------- helpers ----------------------------------------------------
__device__ __forceinline__ float fast_lg2(float x) {
    float r; asm("lg2.approx.f32 %0, %1;" : "=f"(r) : "f"(x)); return r;
}
__device__ __forceinline__ float fast_ex2(float x) {
    float r; asm("ex2.approx.f32 %0, %1;" : "=f"(r) : "f"(x)); return r;
}
__device__ __forceinline__ uint32_t smem_u32(const void* p) {
    uint32_t a;
    asm("{ .reg .u64 t; cvta.to.shared.u64 t, %1; cvt.u32.u64 %0, t; }"
        : "=r"(a) : "l"(p));
    return a;
}
__device__ __forceinline__ uint32_t mapa_u32(uint32_t a, uint32_t r) {
    uint32_t d;
    asm("mapa.shared::cluster.u32 %0, %1, %2;" : "=r"(d) : "r"(a), "r"(r));
    return d;
}

// ---------------- kernel 1: selection logits + softmax ----------------------
__global__ __launch_bounds__(256) void sel_kernel(
    const float* __restrict__ x, const float* __restrict__ Wsel,
    const float* __restrict__ bsel)
{
    __shared__ float Ws[NK * ND];
    for (int i = threadIdx.x; i < NK * ND; i += blockDim.x) Ws[i] = Wsel[i];
    __syncthreads();

    int w = threadIdx.x >> 5, l = threadIdx.x & 31;
    int row = blockIdx.x * 8 + w;
    const float* xr = x + row * ND;

    float p0 = 0.f, p1 = 0.f, p2 = 0.f, p3 = 0.f;
    for (int d = l; d < ND; d += 32) {
        float xv = xr[d];
        p0 += xv * Ws[d];
        p1 += xv * Ws[ND + d];
        p2 += xv * Ws[2 * ND + d];
        p3 += xv * Ws[3 * ND + d];
    }
#pragma unroll
    for (int o = 16; o > 0; o >>= 1) {
        p0 += __shfl_xor_sync(0xffffffffu, p0, o);
        p1 += __shfl_xor_sync(0xffffffffu, p1, o);
        p2 += __shfl_xor_sync(0xffffffffu, p2, o);
        p3 += __shfl_xor_sync(0xffffffffu, p3, o);
    }
    if (l == 0) {
        float l0 = p0 + bsel[0], l1 = p1 + bsel[1], l2 = p2 + bsel[2], l3 = p3 + bsel[3];
        float m = fmaxf(fmaxf(l0, l1), fmaxf(l2, l3));
        float e0 = __expf(l0 - m), e1 = __expf(l1 - m), e2 = __expf(l2 - m), e3 = __expf(l3 - m);
        float inv = 1.0f / (e0 + e1 + e2 + e3);
        float4 out = make_float4(e0 * inv, e1 * inv, e2 * inv, e3 * inv);
        *reinterpret_cast<float4*>(&g_sel[row * NK]) = out;
    }
}

// ---------------- kernel 2: u = x @ W_B^T  (M=16384, N=256, K=512) ----------
__global__ __launch_bounds__(256) void uin_kernel(
    const float* __restrict__ X, const float* __restrict__ Wb)
{
    __shared__ float Xs[16][64];
    __shared__ float Wt[16][64];
    int m0 = blockIdx.y * 64;
    int n0 = blockIdx.x * 64;
    int tid = threadIdx.x;
    int tx = tid & 15, ty = tid >> 4;
    int lr = tid >> 2, lq = tid & 3;

    float acc[4][4];
#pragma unroll
    for (int r = 0; r < 4; r++)
#pragma unroll
        for (int c = 0; c < 4; c++) acc[r][c] = 0.f;

    for (int k0 = 0; k0 < ND; k0 += 16) {
        float4 xv = *reinterpret_cast<const float4*>(&X [(m0 + lr) * ND + k0 + lq * 4]);
        float4 wv = *reinterpret_cast<const float4*>(&Wb[(n0 + lr) * ND + k0 + lq * 4]);
        __syncthreads();
        Xs[lq * 4 + 0][lr] = xv.x; Xs[lq * 4 + 1][lr] = xv.y;
        Xs[lq * 4 + 2][lr] = xv.z; Xs[lq * 4 + 3][lr] = xv.w;
        Wt[lq * 4 + 0][lr] = wv.x; Wt[lq * 4 + 1][lr] = wv.y;
        Wt[lq * 4 + 2][lr] = wv.z; Wt[lq * 4 + 3][lr] = wv.w;
        __syncthreads();
#pragma unroll
        for (int kk = 0; kk < 16; kk++) {
            float4 a = *reinterpret_cast<const float4*>(&Xs[kk][ty * 4]);
            float4 b = *reinterpret_cast<const float4*>(&Wt[kk][tx * 4]);
            acc[0][0] += a.x * b.x; acc[0][1] += a.x * b.y; acc[0][2] += a.x * b.z; acc[0][3] += a.x * b.w;
            acc[1][0] += a.y * b.x; acc[1][1] += a.y * b.y; acc[1][2] += a.y * b.z; acc[1][3] += a.y * b.w;
            acc[2][0] += a.z * b.x; acc[2][1] += a.z * b.y; acc[2][2] += a.z * b.z; acc[2][3] += a.z * b.w;
            acc[3][0] += a.w * b.x; acc[3][1] += a.w * b.y; acc[3][2] += a.w * b.z; acc[3][3] += a.w * b.w;
        }
    }
#pragma unroll
    for (int r = 0; r < 4; r++) {
        float4 o = make_float4(acc[r][0], acc[r][1], acc[r][2], acc[r][3]);
        *reinterpret_cast<float4*>(&g_uin[(m0 + ty * 4 + r) * NH + n0 + tx * 4]) = o;
    }
}

// ---------------- kernel 3: inv_norm pre-pass (register-resident A) ---------
// grid (32 jblocks, 64 rowgroups), 256 threads, 3 CTAs/SM. Warp w owns column
// jbase+w; lane l holds A[l+32r][j][.] in regs. 2 rows per iter to interleave
// the shfl-reduce chains. MUFU-pipe bound.
__global__ __launch_bounds__(256, 3) void norm_kernel(const float* __restrict__ A)
{
    int jbase = blockIdx.x * 8;
    int w = threadIdx.x >> 5, l = threadIdx.x & 31;
    int j = jbase + w;

    float4 Ar[8];
#pragma unroll
    for (int r = 0; r < 8; r++)
        Ar[r] = reinterpret_cast<const float4*>(A)[(l + 32 * r) * NH + j];

    const int rows_per_blk = NROWS / 64;       // 256
    const int row0 = blockIdx.y * rows_per_blk;
    const float ninv = -1.0f / 1.2f;

    for (int row = row0; row < row0 + rows_per_blk; row += 2) {
        float4 sA = __ldg(reinterpret_cast<const float4*>(&g_sel[row * NK]));
        float4 sB = __ldg(reinterpret_cast<const float4*>(&g_sel[(row + 1) * NK]));
        float accA = 0.f, accB = 0.f;
#pragma unroll
        for (int r = 0; r < 8; r++) {
            float a = fmaf(sA.x, Ar[r].x, fmaf(sA.y, Ar[r].y,
                      fmaf(sA.z, Ar[r].z, sA.w * Ar[r].w)));
            float b = fmaf(sB.x, Ar[r].x, fmaf(sB.y, Ar[r].y,
                      fmaf(sB.z, Ar[r].z, sB.w * Ar[r].w)));
            accA += fast_ex2(0.6f * fast_lg2(a * a));
            accB += fast_ex2(0.6f * fast_lg2(b * b));
        }
#pragma unroll
        for (int o = 16; o > 0; o >>= 1) {
            accA += __shfl_xor_sync(0xffffffffu, accA, o);
            accB += __shfl_xor_sync(0xffffffffu, accB, o);
        }
        if (l == 0) {
            g_invn[row * NH + j]       = fast_ex2(fast_lg2(accA) * ninv);
            g_invn[(row + 1) * NH + j] = fast_ex2(fast_lg2(accB) * ninv);
        }
    }
}

// ---------------- kernel 4: scan, 8-CTA cluster, st.async + mbarrier --------
// Cluster = batch. CTA rank owns j in [rank*32, rank*32+32) and rows i in the
// same range. Thread t: row i=t>>1, half=t&1 covers 16 j's. Per step:
//   y = h*inv (warp0, smem bcast) -> bar -> matvec (amix preloaded) ->
//   shfl pair-reduce -> even threads st.async the row partial straight into
//   owner CTA's pbuf[parity] with tx-signal on owner's mbar[parity] ->
//   recompute amix for t+1 in the DSMEM flight shadow -> warp0 try_wait
//   (parity) -> h = u + sum of 8 partials -> out.
// 1024B tx per owner per step (8 CTAs x 32 floats). expect_tx for step t+2 is
// posted right after wait(t): every producer's t+2 store is gated (through its
// own wait(t+1), which needs our t+1 stores, issued after this point), so the
// expect always precedes its transactions. Only ONE __syncthreads per step;
// the mbarrier wait subsumes the bottom sync (stores data-depend on y reads).
__global__ __launch_bounds__(512, 1) __cluster_dims__(8, 1, 1)
void scan_kernel(const float* __restrict__ A, float* __restrict__ out)
{
    __shared__ float y_sm[32];
    __shared__ float pbuf[2][8][32];
    __shared__ __align__(8) unsigned long long mbar[2];

    int tid = threadIdx.x;
    uint32_t rank;
    asm("mov.u32 %0, %%cluster_ctarank;" : "=r"(rank));
    int b = blockIdx.x >> 3;
    int jbase = (int)rank * 32;
    int i = tid >> 1, half = tid & 1;

    float4 Areg[16];
#pragma unroll
    for (int q = 0; q < 16; q++)
        Areg[q] = reinterpret_cast<const float4*>(A)[i * NH + jbase + half * 16 + q];

    // mbarrier setup: count=1 (the consumer's arrive.expect_tx), tx=1024 B/phase
    uint32_t mbar_s = smem_u32(mbar);
    if (tid == 0) {
        asm volatile("mbarrier.init.shared.b64 [%0], 1;" :: "r"(mbar_s) : "memory");
        asm volatile("mbarrier.init.shared.b64 [%0], 1;" :: "r"(mbar_s + 8) : "memory");
    }
    __syncthreads();
    if (tid == 0) {
        asm volatile("mbarrier.arrive.expect_tx.shared.b64 _, [%0], 1024;" :: "r"(mbar_s) : "memory");
        asm volatile("mbarrier.arrive.expect_tx.shared.b64 _, [%0], 1024;" :: "r"(mbar_s + 8) : "memory");
    }
    __syncthreads();
    asm volatile("barrier.cluster.arrive.aligned;" ::: "memory");
    asm volatile("barrier.cluster.wait.aligned;"  ::: "memory");

    // remote addresses for this thread's row partial (owner = i>>5)
    uint32_t dst = (uint32_t)(i >> 5);
    uint32_t laddr0 = smem_u32(pbuf) + (rank * 32u + (uint32_t)(i & 31)) * 4u;
    uint32_t raddr0 = mapa_u32(laddr0, dst);
    uint32_t raddr1 = raddr0 + 8u * 32u * 4u;          // parity-1 buffer
    uint32_t rmbar0 = mapa_u32(mbar_s, dst);
    uint32_t rmbar1 = rmbar0 + 8u;

    const int rowbase = b * NL;
    float4 s0 = __ldg(reinterpret_cast<const float4*>(&g_sel[rowbase * NK]));
    float inv_cur = 0.f, u_cur = 0.f, h_reg = 0.f;
    if (tid < 32) {
        inv_cur = __ldg(&g_invn[rowbase * NH + jbase + tid]);
        u_cur   = __ldg(&g_uin [rowbase * NH + jbase + tid]);
    }

    // amix for t=0
    float amix[16];
#pragma unroll
    for (int q = 0; q < 16; q++)
        amix[q] = fmaf(s0.x, Areg[q].x, fmaf(s0.y, Areg[q].y,
                  fmaf(s0.z, Areg[q].z, s0.w * Areg[q].w)));

    for (int t = 0; t < NL; t++) {
        const int row = rowbase + t;
        if (tid < 32) y_sm[tid] = h_reg * inv_cur;
        __syncthreads();

        // prefetch next-step row data
        const int rown = row + (t < NL - 1 ? 1 : 0);
        float4 s_nxt = __ldg(reinterpret_cast<const float4*>(&g_sel[rown * NK]));
        float inv_nxt = 0.f, u_nxt = 0.f;
        if (tid < 32) {
            inv_nxt = __ldg(&g_invn[rown * NH + jbase + tid]);
            u_nxt   = __ldg(&g_uin [rown * NH + jbase + tid]);
        }

        float acc = 0.f;
#pragma unroll
        for (int q = 0; q < 16; q++)
            acc = fmaf(amix[q], y_sm[half * 16 + q], acc);
        acc += __shfl_xor_sync(0xffffffffu, acc, 1);

        if (half == 0) {
            uint32_t ra = (t & 1) ? raddr1 : raddr0;
            uint32_t rm = (t & 1) ? rmbar1 : rmbar0;
            asm volatile(
                "st.async.shared::cluster.mbarrier::complete_tx::bytes.b32 [%0], %1, [%2];"
                :: "r"(ra), "r"(__float_as_uint(acc)), "r"(rm) : "memory");
        }

        // hide DSMEM flight: compute amix for t+1
#pragma unroll
        for (int q = 0; q < 16; q++)
            amix[q] = fmaf(s_nxt.x, Areg[q].x, fmaf(s_nxt.y, Areg[q].y,
                      fmaf(s_nxt.z, Areg[q].z, s_nxt.w * Areg[q].w)));

        if (tid < 32) {
            uint32_t mb = mbar_s + (uint32_t)((t & 1) * 8);
            uint32_t ph = (uint32_t)((t >> 1) & 1);
            asm volatile(
                "{\n\t.reg .pred p;\n"
                "WL%=:\n\t"
                "mbarrier.try_wait.parity.acquire.cluster.shared::cta.b64 p, [%0], %1;\n\t"
                "@!p bra WL%=;\n\t}"
                :: "r"(mb), "r"(ph) : "memory");
            if (tid == 0 && t + 2 < NL)
                asm volatile("mbarrier.arrive.expect_tx.shared.b64 _, [%0], 1024;"
                             :: "r"(mb) : "memory");
            float hv = u_cur;
            const float* pb = &pbuf[t & 1][0][tid];
#pragma unroll
            for (int ss = 0; ss < 8; ss++) hv += pb[ss * 32];
            out[row * NH + jbase + tid] = hv;
            h_reg = hv;
            inv_cur = inv_nxt;
            u_cur = u_nxt;
        }
    }

    // keep cluster alive until all CTAs consumed their last partials
    asm volatile("barrier.cluster.arrive.aligned;" ::: "memory");
    asm volatile("barrier.cluster.wait.aligned;"  ::: "memory");
}

// ---------------- launch ----------------------------------------------------
extern "C" void kernel_launch(void* const* d_in, const int* in_sizes, int n_in,
                              void* d_out, int out_size)
{
    const float* x     = (const float*)d_in[0];   // (16,1024,512)
    const float* Wsel  = (const float*)d_in[1];   // (4,512)
    const float* bsel  = (const float*)d_in[2];   // (4,)
    const float* Wb    = (const float*)d_in[3];   // (256,512)
    const float* Adict = (const float*)d_in[4];   // (256,256,4)
    float* out = (float*)d_out;                   // (16,1024,256)

    sel_kernel<<<NROWS / 8, 256>>>(x, Wsel, bsel);
    uin_kernel<<<dim3(NH / 64, NROWS / 64), 256>>>(x, Wb);
    norm_kernel<<<dim3(32, 64), 256>>>(Adict);
    scan_kernel<<<NB * 8, 512>>>(Adict, out);
}